// round 8
// baseline (speedup 1.0000x reference)
#include <cuda_runtime.h>
#include <cuda_fp16.h>
#include <math.h>
#include <stdint.h>

#define B_    2
#define H_    16
#define E_    1024
#define D_    64
#define BH_   32
#define NSEQ  2048

// ---------------- scratch (float units; halves live inside) ------------------
static const size_t OFF_AQ   = 0;                   // half [32][2048][64]
static const size_t OFF_BQ   = OFF_AQ   + 2097152;
static const size_t OFF_AVT  = OFF_BQ   + 2097152;  // half [32][64][2048]
static const size_t OFF_BVT  = OFF_AVT  + 2097152;
static const size_t OFF_ACTX = OFF_BVT  + 2097152;  // half [32][2048][64]
static const size_t OFF_BCTX = OFF_ACTX + 2097152;
static const size_t OFF_ATH  = OFF_BCTX + 2097152;  // half [4096][1024]
static const size_t OFF_BTH  = OFF_ATH  + 2097152;
static const size_t OFF_WT   = OFF_BTH  + 2097152;  // 6x half [1024n][1024k]
static const size_t SCRATCH_ELEMS = OFF_WT + 6 * 524288;
__device__ float g_scratch[SCRATCH_ELEMS];

// ---------------- helpers ----------------------------------------------------
__device__ __forceinline__ float ex2f(float x) {
    float y;
    asm("ex2.approx.f32 %0, %1;" : "=f"(y) : "f"(x));
    return y;
}
#define CEXP 0.18033688011112042f   // log2(e)/8 : exp(s/8) = 2^(s*CEXP)

__device__ __forceinline__ uint32_t pack_h2(float lo, float hi) {
    __half2 h = __floats2half2_rn(lo, hi);
    return *reinterpret_cast<uint32_t*>(&h);
}

__device__ __forceinline__ uint32_t smem_u32(const void* p) {
    uint32_t a;
    asm("{ .reg .u64 t; cvta.to.shared.u64 t, %1; cvt.u32.u64 %0, t; }" : "=r"(a) : "l"(p));
    return a;
}

__device__ __forceinline__ void mma_h(float c[4], const uint32_t a[4],
                                      uint32_t b0, uint32_t b1) {
    asm volatile(
        "mma.sync.aligned.m16n8k16.row.col.f32.f16.f16.f32 "
        "{%0,%1,%2,%3}, {%4,%5,%6,%7}, {%8,%9}, {%0,%1,%2,%3};"
        : "+f"(c[0]), "+f"(c[1]), "+f"(c[2]), "+f"(c[3])
        : "r"(a[0]), "r"(a[1]), "r"(a[2]), "r"(a[3]), "r"(b0), "r"(b1));
}

#define LDMX4(r0, r1, r2, r3, addr) \
    asm volatile("ldmatrix.sync.aligned.m8n8.x4.shared.b16 {%0,%1,%2,%3}, [%4];" \
        : "=r"(r0), "=r"(r1), "=r"(r2), "=r"(r3) : "r"(addr))

__device__ __forceinline__ void cp16(uint32_t dst, const void* src) {
    asm volatile("cp.async.cg.shared.global [%0], [%1], 16;" :: "r"(dst), "l"(src) : "memory");
}
#define CP_COMMIT() asm volatile("cp.async.commit_group;" ::: "memory")
#define CP_WAIT0()  asm volatile("cp.async.wait_group 0;" ::: "memory")
#define CP_WAIT2()  asm volatile("cp.async.wait_group 2;" ::: "memory")

// ---------------- merged prologue: cvt a,b + 6 weight transposes -------------
struct PrepArgs {
    const float *a, *b, *W0, *W1, *W2, *W3, *W4, *W5;
    __half *aTh, *bTh, *wTh;
};

__global__ __launch_bounds__(256) void prep_kernel(PrepArgs pa)
{
    __shared__ float tile[32][33];
    const int z = blockIdx.z;
    const int tid = threadIdx.x;
    if (z < 2) {
        const float4* src = (const float4*)(z ? pa.b : pa.a);
        uint2* dst = (uint2*)(z ? pa.bTh : pa.aTh);
        int i = (blockIdx.y * 32 + blockIdx.x) * 256 + tid;
        #pragma unroll
        for (int r = 0; r < 4; r++) {
            float4 v = src[i];
            uint2 o = { pack_h2(v.x, v.y), pack_h2(v.z, v.w) };
            dst[i] = o;
            i += 262144;
        }
    } else {
        const float* W = (z == 2) ? pa.W0 : (z == 3) ? pa.W1 : (z == 4) ? pa.W2 :
                         (z == 5) ? pa.W3 : (z == 6) ? pa.W4 : pa.W5;
        __half* Wt = pa.wTh + (size_t)(z - 2) * 1048576;
        const int n0 = blockIdx.x * 32, k0 = blockIdx.y * 32;
        const int tx = tid & 31, ty = tid >> 5;
        #pragma unroll
        for (int j = 0; j < 4; j++)
            tile[ty + 8 * j][tx] = W[(size_t)(k0 + ty + 8 * j) * E_ + n0 + tx];
        __syncthreads();
        #pragma unroll
        for (int j = 0; j < 4; j++)
            Wt[(size_t)(n0 + ty + 8 * j) * E_ + k0 + tx] = __float2half_rn(tile[tx][ty + 8 * j]);
    }
}

// ================= fp16 GEMMs: 4-stage cp.async, k-tile 32 ==================
// Row = 32 halfs = 4x16B chunks, pad to 20 words (bank-permute (r*5)%8).
#define GW 20
#define GSTG_WORDS 5120                 // A(2560) + B(2560) per stage
#define GEMM_SMEM (4*GSTG_WORDS*4)      // 81920 bytes -> 2 CTA/SM
#define NKT 32                          // 1024 / 32

struct PArgs { const __half* X; const __half* Wt; const float* bias; __half* out; int vmode; };
struct PArgs4 { PArgs p[4]; };
struct OArgs { const __half* ctx; const __half* Wt; const float* bias; float* out; };
struct OArgs2 { OArgs p[2]; };

__global__ __launch_bounds__(256, 2) void projh_kernel(PArgs4 args)
{
    const PArgs pa = args.p[blockIdx.z];
    extern __shared__ uint32_t smw[];
    const uint32_t smb = smem_u32(smw);

    const int tid  = threadIdx.x;
    const int lane = tid & 31;
    const int warp = tid >> 5;
    const int g = lane >> 2, t = lane & 3;
    const int l8 = lane & 7, quad = lane >> 3;
    const int wm = warp & 3, wn = warp >> 2;
    const int row0 = blockIdx.y * 128;
    const int col0 = blockIdx.x * 128;

    const uint32_t aoff = (uint32_t)((((quad & 1) * 8 + l8) * GW + (quad >> 1) * 4) * 4);
    const uint32_t boff = (uint32_t)((((quad >> 1) * 8 + l8) * GW + (quad & 1) * 4) * 4);
    const int lr = tid >> 2, lc = tid & 3;   // loader: row, chunk (2 rows-passes)

    float acc[2][8][4];
    #pragma unroll
    for (int i = 0; i < 2; i++)
        #pragma unroll
        for (int n = 0; n < 8; n++)
            #pragma unroll
            for (int j = 0; j < 4; j++) acc[i][n][j] = 0.0f;

    // prefetch stages 0..2
    #pragma unroll
    for (int s = 0; s < 3; s++) {
        int k0 = s * 32;
        uint32_t sb = smb + (uint32_t)(s * GSTG_WORDS) * 4;
        #pragma unroll
        for (int p = 0; p < 2; p++) {
            int r = lr + p * 64;
            cp16(sb + (uint32_t)(r * GW + lc * 4) * 4, pa.X + (size_t)(row0 + r) * E_ + k0 + lc * 8);
            cp16(sb + (uint32_t)(2560 + r * GW + lc * 4) * 4, pa.Wt + (size_t)(col0 + r) * E_ + k0 + lc * 8);
        }
        CP_COMMIT();
    }

    for (int kt = 0; kt < NKT; kt++) {
        CP_WAIT2();
        __syncthreads();
        if (kt + 3 < NKT) {
            int k0 = (kt + 3) * 32;
            uint32_t sb = smb + (uint32_t)(((kt + 3) & 3) * GSTG_WORDS) * 4;
            #pragma unroll
            for (int p = 0; p < 2; p++) {
                int r = lr + p * 64;
                cp16(sb + (uint32_t)(r * GW + lc * 4) * 4, pa.X + (size_t)(row0 + r) * E_ + k0 + lc * 8);
                cp16(sb + (uint32_t)(2560 + r * GW + lc * 4) * 4, pa.Wt + (size_t)(col0 + r) * E_ + k0 + lc * 8);
            }
        }
        CP_COMMIT();

        const uint32_t aBuf = smb + (uint32_t)((kt & 3) * GSTG_WORDS) * 4;
        const uint32_t bBuf = aBuf + 2560 * 4;
        #pragma unroll
        for (int kk = 0; kk < 2; kk++) {
            uint32_t af[2][4];
            LDMX4(af[0][0], af[0][1], af[0][2], af[0][3],
                  aBuf + aoff + (uint32_t)((wm * 32) * GW + kk * 8) * 4);
            LDMX4(af[1][0], af[1][1], af[1][2], af[1][3],
                  aBuf + aoff + (uint32_t)((wm * 32 + 16) * GW + kk * 8) * 4);
            #pragma unroll
            for (int j = 0; j < 4; j++) {
                uint32_t r0, r1, r2, r3;
                LDMX4(r0, r1, r2, r3,
                      bBuf + boff + (uint32_t)((wn * 64 + j * 16) * GW + kk * 8) * 4);
                mma_h(acc[0][2 * j],     af[0], r0, r1);
                mma_h(acc[0][2 * j + 1], af[0], r2, r3);
                mma_h(acc[1][2 * j],     af[1], r0, r1);
                mma_h(acc[1][2 * j + 1], af[1], r2, r3);
            }
        }
    }

    if (!pa.vmode) {
        #pragma unroll
        for (int i = 0; i < 2; i++) {
            int m = row0 + wm * 32 + i * 16;
            int bb = m >> 11, ii = m & 2047;
            #pragma unroll
            for (int n = 0; n < 8; n++) {
                int col = col0 + wn * 64 + n * 8 + 2 * t;
                int h = col >> 6, d = col & 63;
                float2 bi = *reinterpret_cast<const float2*>(pa.bias + col);
                __half* base = pa.out + ((size_t)(bb * H_ + h) * NSEQ) * D_ + d;
                *reinterpret_cast<uint32_t*>(base + (size_t)(ii + g) * D_) =
                    pack_h2(acc[i][n][0] + bi.x, acc[i][n][1] + bi.y);
                *reinterpret_cast<uint32_t*>(base + (size_t)(ii + g + 8) * D_) =
                    pack_h2(acc[i][n][2] + bi.x, acc[i][n][3] + bi.y);
            }
        }
    } else {
        #pragma unroll
        for (int i = 0; i < 2; i++) {
            int m = row0 + wm * 32 + i * 16;
            int bb = m >> 11, ii = m & 2047;
            #pragma unroll
            for (int n = 0; n < 8; n++) {
                int col = col0 + wn * 64 + n * 8 + 2 * t;
                int h = col >> 6, d = col & 63;
                float2 bi = *reinterpret_cast<const float2*>(pa.bias + col);
                __half* base = pa.out + ((size_t)(bb * H_ + h) * D_) * NSEQ;
                base[(size_t)d * NSEQ + ii + g]           = __float2half_rn(acc[i][n][0] + bi.x);
                base[(size_t)(d + 1) * NSEQ + ii + g]     = __float2half_rn(acc[i][n][1] + bi.y);
                base[(size_t)d * NSEQ + ii + g + 8]       = __float2half_rn(acc[i][n][2] + bi.x);
                base[(size_t)(d + 1) * NSEQ + ii + g + 8] = __float2half_rn(acc[i][n][3] + bi.y);
            }
        }
    }
}

__global__ __launch_bounds__(256, 2) void outh_kernel(OArgs2 args)
{
    const OArgs pa = args.p[blockIdx.z];
    extern __shared__ uint32_t smw[];
    const uint32_t smb = smem_u32(smw);

    const int tid  = threadIdx.x;
    const int lane = tid & 31;
    const int warp = tid >> 5;
    const int g = lane >> 2, t = lane & 3;
    const int l8 = lane & 7, quad = lane >> 3;
    const int wm = warp & 3, wn = warp >> 2;
    const int row0 = blockIdx.y * 128;
    const int col0 = blockIdx.x * 128;

    const uint32_t aoff = (uint32_t)((((quad & 1) * 8 + l8) * GW + (quad >> 1) * 4) * 4);
    const uint32_t boff = (uint32_t)((((quad >> 1) * 8 + l8) * GW + (quad & 1) * 4) * 4);
    const int lr = tid >> 2, lc = tid & 3;

    float acc[2][8][4];
    #pragma unroll
    for (int i = 0; i < 2; i++)
        #pragma unroll
        for (int n = 0; n < 8; n++)
            #pragma unroll
            for (int j = 0; j < 4; j++) acc[i][n][j] = 0.0f;

    // ctx A-gather: k-tile of 32 spans half a head; head h = k0>>6, d = k0&63
    #pragma unroll
    for (int s = 0; s < 3; s++) {
        int k0 = s * 32;
        int h = k0 >> 6, d0 = k0 & 63;
        uint32_t sb = smb + (uint32_t)(s * GSTG_WORDS) * 4;
        #pragma unroll
        for (int p = 0; p < 2; p++) {
            int r = lr + p * 64;
            int m = row0 + r, bb = m >> 11, ii = m & 2047;
            cp16(sb + (uint32_t)(r * GW + lc * 4) * 4,
                 pa.ctx + ((size_t)(bb * H_ + h) * NSEQ + ii) * D_ + d0 + lc * 8);
            cp16(sb + (uint32_t)(2560 + r * GW + lc * 4) * 4,
                 pa.Wt + (size_t)(col0 + r) * E_ + k0 + lc * 8);
        }
        CP_COMMIT();
    }

    for (int kt = 0; kt < NKT; kt++) {
        CP_WAIT2();
        __syncthreads();
        if (kt + 3 < NKT) {
            int k0 = (kt + 3) * 32;
            int h = k0 >> 6, d0 = k0 & 63;
            uint32_t sb = smb + (uint32_t)(((kt + 3) & 3) * GSTG_WORDS) * 4;
            #pragma unroll
            for (int p = 0; p < 2; p++) {
                int r = lr + p * 64;
                int m = row0 + r, bb = m >> 11, ii = m & 2047;
                cp16(sb + (uint32_t)(r * GW + lc * 4) * 4,
                     pa.ctx + ((size_t)(bb * H_ + h) * NSEQ + ii) * D_ + d0 + lc * 8);
                cp16(sb + (uint32_t)(2560 + r * GW + lc * 4) * 4,
                     pa.Wt + (size_t)(col0 + r) * E_ + k0 + lc * 8);
            }
        }
        CP_COMMIT();

        const uint32_t aBuf = smb + (uint32_t)((kt & 3) * GSTG_WORDS) * 4;
        const uint32_t bBuf = aBuf + 2560 * 4;
        #pragma unroll
        for (int kk = 0; kk < 2; kk++) {
            uint32_t af[2][4];
            LDMX4(af[0][0], af[0][1], af[0][2], af[0][3],
                  aBuf + aoff + (uint32_t)((wm * 32) * GW + kk * 8) * 4);
            LDMX4(af[1][0], af[1][1], af[1][2], af[1][3],
                  aBuf + aoff + (uint32_t)((wm * 32 + 16) * GW + kk * 8) * 4);
            #pragma unroll
            for (int j = 0; j < 4; j++) {
                uint32_t r0, r1, r2, r3;
                LDMX4(r0, r1, r2, r3,
                      bBuf + boff + (uint32_t)((wn * 64 + j * 16) * GW + kk * 8) * 4);
                mma_h(acc[0][2 * j],     af[0], r0, r1);
                mma_h(acc[0][2 * j + 1], af[0], r2, r3);
                mma_h(acc[1][2 * j],     af[1], r0, r1);
                mma_h(acc[1][2 * j + 1], af[1], r2, r3);
            }
        }
    }

    #pragma unroll
    for (int i = 0; i < 2; i++) {
        int m = row0 + wm * 32 + i * 16;
        #pragma unroll
        for (int n = 0; n < 8; n++) {
            int c = col0 + wn * 64 + n * 8 + 2 * t;
            float2 bi = *reinterpret_cast<const float2*>(pa.bias + c);
            float2 lo = { acc[i][n][0] + bi.x, acc[i][n][1] + bi.y };
            float2 hi = { acc[i][n][2] + bi.x, acc[i][n][3] + bi.y };
            *reinterpret_cast<float2*>(pa.out + (size_t)(m + g) * E_ + c) = lo;
            *reinterpret_cast<float2*>(pa.out + (size_t)(m + g + 8) * E_ + c) = hi;
        }
    }
}

// ================= fused flash kernel: register-passed P =====================
#define FQW 36
#define FVW 68
#define FSQ   0
#define FSKa  4608
#define FSVa  13824
#define FLASH_WORDS 22528
#define FLASH_SMEM  (FLASH_WORDS*4)   // 90112 bytes -> 2 CTA/SM

__global__ __launch_bounds__(256, 2) void flashh_kernel(
    const __half* __restrict__ aq, const __half* __restrict__ bq,
    const __half* __restrict__ avt, const __half* __restrict__ bvt,
    __half* __restrict__ actx, __half* __restrict__ bctx)
{
    extern __shared__ uint32_t smw[];
    const uint32_t smb = smem_u32(smw);

    const int tid  = threadIdx.x;
    const int lane = tid & 31;
    const int warp = tid >> 5;
    const int g = lane >> 2, t = lane & 3;
    const int l8 = lane & 7, quad = lane >> 3;
    const int m0 = warp * 16;

    const int side = blockIdx.z;
    const int bh   = blockIdx.y;
    const int row0 = blockIdx.x * 128;

    const __half* Qg  = (side ? bq : aq) + (size_t)bh * NSEQ * D_;
    const __half* Kg  = (side ? aq : bq) + (size_t)bh * NSEQ * D_;
    const __half* Vtg = (side ? avt : bvt) + (size_t)bh * D_ * NSEQ;
    __half* Og = (side ? bctx : actx) + (size_t)bh * NSEQ * D_;

    const uint32_t koff = (uint32_t)((((quad >> 1) * 8 + l8) * FQW + (quad & 1) * 4) * 4);
    const uint32_t voff = (uint32_t)((((quad >> 1) * 8 + l8) * FVW + (quad & 1) * 4) * 4);

    #pragma unroll
    for (int p = 0; p < 4; p++) {
        int idx = p * 256 + tid, r = idx >> 3, c = idx & 7;
        cp16(smb + (uint32_t)(FSQ + r * FQW + c * 4) * 4, Qg + (size_t)(row0 + r) * D_ + c * 8);
    }
    #pragma unroll
    for (int p = 0; p < 4; p++) {
        int idx = p * 256 + tid, r = idx >> 3, c = idx & 7;
        cp16(smb + (uint32_t)(FSKa + r * FQW + c * 4) * 4, Kg + (size_t)r * D_ + c * 8);
    }
    #pragma unroll
    for (int p = 0; p < 4; p++) {
        int idx = p * 256 + tid, r = idx >> 4, c = idx & 15;
        cp16(smb + (uint32_t)(FSVa + r * FVW + c * 4) * 4, Vtg + (size_t)r * NSEQ + c * 8);
    }
    CP_COMMIT();

    uint32_t Qf[4][4];
    float Oacc[8][4];
    #pragma unroll
    for (int n = 0; n < 8; n++)
        #pragma unroll
        for (int j = 0; j < 4; j++) Oacc[n][j] = 0.0f;
    float rsum0 = 0.0f, rsum1 = 0.0f;

    int buf = 0;
    for (int kt = 0; kt < 16; kt++) {
        CP_WAIT0();
        __syncthreads();
        if (kt == 0) {
            #pragma unroll
            for (int kk = 0; kk < 4; kk++) {
                Qf[kk][0] = smw[FSQ + (m0 + g) * FQW + kk * 8 + t];
                Qf[kk][1] = smw[FSQ + (m0 + g + 8) * FQW + kk * 8 + t];
                Qf[kk][2] = smw[FSQ + (m0 + g) * FQW + kk * 8 + t + 4];
                Qf[kk][3] = smw[FSQ + (m0 + g + 8) * FQW + kk * 8 + t + 4];
            }
        }
        if (kt < 15) {
            int key0 = (kt + 1) * 128;
            int nb = buf ^ 1;
            #pragma unroll
            for (int p = 0; p < 4; p++) {
                int idx = p * 256 + tid, r = idx >> 3, c = idx & 7;
                cp16(smb + (uint32_t)(FSKa + nb * 4608 + r * FQW + c * 4) * 4,
                     Kg + (size_t)(key0 + r) * D_ + c * 8);
            }
            #pragma unroll
            for (int p = 0; p < 4; p++) {
                int idx = p * 256 + tid, r = idx >> 4, c = idx & 15;
                cp16(smb + (uint32_t)(FSVa + nb * 4352 + r * FVW + c * 4) * 4,
                     Vtg + (size_t)r * NSEQ + key0 + c * 8);
            }
            CP_COMMIT();
        }

        const uint32_t kbase = smb + (uint32_t)(FSKa + buf * 4608) * 4 + koff;
        const uint32_t vbase = smb + (uint32_t)(FSVa + buf * 4352) * 4 + voff;

        #pragma unroll
        for (int kk = 0; kk < 8; kk++) {
            float slo[4] = {0.f, 0.f, 0.f, 0.f};
            float shi[4] = {0.f, 0.f, 0.f, 0.f};
            #pragma unroll
            for (int c = 0; c < 4; c++) {
                uint32_t r0, r1, r2, r3;
                LDMX4(r0, r1, r2, r3, kbase + (uint32_t)((16 * kk) * FQW + c * 8) * 4);
                mma_h(slo, Qf[c], r0, r1);
                mma_h(shi, Qf[c], r2, r3);
            }
            float e0 = ex2f(slo[0] * CEXP), e1 = ex2f(slo[1] * CEXP);
            float e2 = ex2f(slo[2] * CEXP), e3 = ex2f(slo[3] * CEXP);
            float f0 = ex2f(shi[0] * CEXP), f1 = ex2f(shi[1] * CEXP);
            float f2 = ex2f(shi[2] * CEXP), f3 = ex2f(shi[3] * CEXP);
            rsum0 += (e0 + e1) + (f0 + f1);
            rsum1 += (e2 + e3) + (f2 + f3);
            uint32_t a[4] = { pack_h2(e0, e1), pack_h2(e2, e3),
                              pack_h2(f0, f1), pack_h2(f2, f3) };
            #pragma unroll
            for (int j = 0; j < 4; j++) {
                uint32_t r0, r1, r2, r3;
                LDMX4(r0, r1, r2, r3, vbase + (uint32_t)((16 * j) * FVW + kk * 8) * 4);
                mma_h(Oacc[2 * j],     a, r0, r1);
                mma_h(Oacc[2 * j + 1], a, r2, r3);
            }
        }
        buf ^= 1;
    }

    rsum0 += __shfl_xor_sync(0xffffffffu, rsum0, 1);
    rsum0 += __shfl_xor_sync(0xffffffffu, rsum0, 2);
    rsum1 += __shfl_xor_sync(0xffffffffu, rsum1, 1);
    rsum1 += __shfl_xor_sync(0xffffffffu, rsum1, 2);
    float inv0 = 1.0f / rsum0;
    float inv1 = 1.0f / rsum1;

    __half* r0p = Og + (size_t)(row0 + m0 + g) * D_;
    __half* r1p = Og + (size_t)(row0 + m0 + g + 8) * D_;
    #pragma unroll
    for (int n = 0; n < 8; n++) {
        *reinterpret_cast<uint32_t*>(r0p + n * 8 + 2 * t) =
            pack_h2(Oacc[n][0] * inv0, Oacc[n][1] * inv0);
        *reinterpret_cast<uint32_t*>(r1p + n * 8 + 2 * t) =
            pack_h2(Oacc[n][2] * inv1, Oacc[n][3] * inv1);
    }
}

// ---------------------------------------------------------------------------
extern "C" void kernel_launch(void* const* d_in, const int* in_sizes, int n_in,
                              void* d_out, int out_size)
{
    (void)in_sizes; (void)n_in; (void)out_size;
    const float* a     = (const float*)d_in[0];
    const float* b     = (const float*)d_in[1];
    const float* Wa_qk = (const float*)d_in[2];
    const float* ba_qk = (const float*)d_in[3];
    const float* Wa_v  = (const float*)d_in[4];
    const float* ba_v  = (const float*)d_in[5];
    const float* Wb_qk = (const float*)d_in[6];
    const float* bb_qk = (const float*)d_in[7];
    const float* Wb_v  = (const float*)d_in[8];
    const float* bb_v  = (const float*)d_in[9];
    const float* Wa_o  = (const float*)d_in[10];
    const float* ba_o  = (const float*)d_in[11];
    const float* Wb_o  = (const float*)d_in[12];
    const float* bb_o  = (const float*)d_in[13];
    float* out = (float*)d_out;

    float* scratch = nullptr;
    cudaGetSymbolAddress((void**)&scratch, g_scratch);
    __half* aqh  = (__half*)(scratch + OFF_AQ);
    __half* bqh  = (__half*)(scratch + OFF_BQ);
    __half* avt  = (__half*)(scratch + OFF_AVT);
    __half* bvt  = (__half*)(scratch + OFF_BVT);
    __half* actx = (__half*)(scratch + OFF_ACTX);
    __half* bctx = (__half*)(scratch + OFF_BCTX);
    __half* aTh  = (__half*)(scratch + OFF_ATH);
    __half* bTh  = (__half*)(scratch + OFF_BTH);
    __half* wTh  = (__half*)(scratch + OFF_WT);

    cudaFuncSetAttribute(projh_kernel,  cudaFuncAttributeMaxDynamicSharedMemorySize, GEMM_SMEM);
    cudaFuncSetAttribute(outh_kernel,   cudaFuncAttributeMaxDynamicSharedMemorySize, GEMM_SMEM);
    cudaFuncSetAttribute(flashh_kernel, cudaFuncAttributeMaxDynamicSharedMemorySize, FLASH_SMEM);

    PrepArgs prep = { a, b, Wa_qk, Wa_v, Wb_qk, Wb_v, Wa_o, Wb_o, aTh, bTh, wTh };
    prep_kernel<<<dim3(32, 32, 8), 256>>>(prep);

    PArgs4 pargs;
    pargs.p[0] = { aTh, wTh + 0 * 1048576, ba_qk, aqh, 0 };
    pargs.p[1] = { aTh, wTh + 1 * 1048576, ba_v,  avt, 1 };
    pargs.p[2] = { bTh, wTh + 2 * 1048576, bb_qk, bqh, 0 };
    pargs.p[3] = { bTh, wTh + 3 * 1048576, bb_v,  bvt, 1 };
    projh_kernel<<<dim3(E_ / 128, (B_ * NSEQ) / 128, 4), 256, GEMM_SMEM>>>(pargs);

    flashh_kernel<<<dim3(16, BH_, 2), 256, FLASH_SMEM>>>(aqh, bqh, avt, bvt, actx, bctx);

    OArgs2 oargs;
    oargs.p[0] = { actx, wTh + 4 * 1048576, ba_o, out };
    oargs.p[1] = { bctx, wTh + 5 * 1048576, bb_o, out + (size_t)B_ * NSEQ * E_ };
    outh_kernel<<<dim3(E_ / 128, (B_ * NSEQ) / 128, 2), 256, GEMM_SMEM>>>(oargs);
}

// round 9
// speedup vs baseline: 1.0156x; 1.0156x over previous
#include <cuda_runtime.h>
#include <cuda_fp16.h>
#include <math.h>
#include <stdint.h>

#define B_    2
#define H_    16
#define E_    1024
#define D_    64
#define BH_   32
#define NSEQ  2048

// ---------------- scratch (float units; halves live inside) ------------------
static const size_t OFF_AQ   = 0;                   // half [32][2048][64]
static const size_t OFF_BQ   = OFF_AQ   + 2097152;
static const size_t OFF_AVT  = OFF_BQ   + 2097152;  // half [32][64][2048]
static const size_t OFF_BVT  = OFF_AVT  + 2097152;
static const size_t OFF_ACTX = OFF_BVT  + 2097152;  // half [32][2048][64]
static const size_t OFF_BCTX = OFF_ACTX + 2097152;
static const size_t OFF_ATH  = OFF_BCTX + 2097152;  // half [4096][1024]
static const size_t OFF_BTH  = OFF_ATH  + 2097152;
static const size_t OFF_WT   = OFF_BTH  + 2097152;  // 6x half [1024n][1024k]
static const size_t SCRATCH_ELEMS = OFF_WT + 6 * 524288;
__device__ float g_scratch[SCRATCH_ELEMS];

// ---------------- helpers ----------------------------------------------------
__device__ __forceinline__ float ex2f(float x) {
    float y;
    asm("ex2.approx.f32 %0, %1;" : "=f"(y) : "f"(x));
    return y;
}
#define CEXP 0.18033688011112042f   // log2(e)/8 : exp(s/8) = 2^(s*CEXP)

__device__ __forceinline__ uint32_t pack_h2(float lo, float hi) {
    __half2 h = __floats2half2_rn(lo, hi);
    return *reinterpret_cast<uint32_t*>(&h);
}

__device__ __forceinline__ uint32_t smem_u32(const void* p) {
    uint32_t a;
    asm("{ .reg .u64 t; cvta.to.shared.u64 t, %1; cvt.u32.u64 %0, t; }" : "=r"(a) : "l"(p));
    return a;
}

__device__ __forceinline__ void mma_h(float c[4], const uint32_t a[4],
                                      uint32_t b0, uint32_t b1) {
    asm volatile(
        "mma.sync.aligned.m16n8k16.row.col.f32.f16.f16.f32 "
        "{%0,%1,%2,%3}, {%4,%5,%6,%7}, {%8,%9}, {%0,%1,%2,%3};"
        : "+f"(c[0]), "+f"(c[1]), "+f"(c[2]), "+f"(c[3])
        : "r"(a[0]), "r"(a[1]), "r"(a[2]), "r"(a[3]), "r"(b0), "r"(b1));
}

#define LDMX4(r0, r1, r2, r3, addr) \
    asm volatile("ldmatrix.sync.aligned.m8n8.x4.shared.b16 {%0,%1,%2,%3}, [%4];" \
        : "=r"(r0), "=r"(r1), "=r"(r2), "=r"(r3) : "r"(addr))

__device__ __forceinline__ void cp16(uint32_t dst, const void* src) {
    asm volatile("cp.async.cg.shared.global [%0], [%1], 16;" :: "r"(dst), "l"(src) : "memory");
}
#define CP_COMMIT() asm volatile("cp.async.commit_group;" ::: "memory")
#define CP_WAIT0()  asm volatile("cp.async.wait_group 0;" ::: "memory")
#define CP_WAIT1()  asm volatile("cp.async.wait_group 1;" ::: "memory")

// ---------------- merged prologue: cvt a,b + 6 weight transposes -------------
struct PrepArgs {
    const float *a, *b, *W0, *W1, *W2, *W3, *W4, *W5;
    __half *aTh, *bTh, *wTh;
};

__global__ __launch_bounds__(256) void prep_kernel(PrepArgs pa)
{
    __shared__ float tile[32][33];
    const int z = blockIdx.z;
    const int tid = threadIdx.x;
    if (z < 2) {
        const float4* src = (const float4*)(z ? pa.b : pa.a);
        uint2* dst = (uint2*)(z ? pa.bTh : pa.aTh);
        int i = (blockIdx.y * 32 + blockIdx.x) * 256 + tid;
        #pragma unroll
        for (int r = 0; r < 4; r++) {
            float4 v = src[i];
            uint2 o = { pack_h2(v.x, v.y), pack_h2(v.z, v.w) };
            dst[i] = o;
            i += 262144;
        }
    } else {
        const float* W = (z == 2) ? pa.W0 : (z == 3) ? pa.W1 : (z == 4) ? pa.W2 :
                         (z == 5) ? pa.W3 : (z == 6) ? pa.W4 : pa.W5;
        __half* Wt = pa.wTh + (size_t)(z - 2) * 1048576;
        const int n0 = blockIdx.x * 32, k0 = blockIdx.y * 32;
        const int tx = tid & 31, ty = tid >> 5;
        #pragma unroll
        for (int j = 0; j < 4; j++)
            tile[ty + 8 * j][tx] = W[(size_t)(k0 + ty + 8 * j) * E_ + n0 + tx];
        __syncthreads();
        #pragma unroll
        for (int j = 0; j < 4; j++)
            Wt[(size_t)(n0 + ty + 8 * j) * E_ + k0 + tx] = __float2half_rn(tile[tx][ty + 8 * j]);
    }
}

// ================= fp16 GEMMs: 3-stage cp.async, k-tile 64 ==================
// Row = 64 halfs = 8x16B chunks, pad to 36 words -> conflict-free ldmatrix.
#define GW 36
#define GA_WORDS (128*GW)              // 4608 words A per stage
#define GSTG_WORDS (2*GA_WORDS)        // 9216 words per stage (A + B)
#define GEMM_SMEM (3*GSTG_WORDS*4)     // 110592 bytes -> 2 CTA/SM
#define NKT 16                          // 1024 / 64

struct PArgs { const __half* X; const __half* Wt; const float* bias; __half* out; int vmode; };
struct PArgs4 { PArgs p[4]; };
struct OArgs { const __half* ctx; const __half* Wt; const float* bias; float* out; };
struct OArgs2 { OArgs p[2]; };

__global__ __launch_bounds__(256, 2) void projh_kernel(PArgs4 args)
{
    const PArgs pa = args.p[blockIdx.z];
    extern __shared__ uint32_t smw[];
    const uint32_t smb = smem_u32(smw);

    const int tid  = threadIdx.x;
    const int lane = tid & 31;
    const int warp = tid >> 5;
    const int g = lane >> 2, t = lane & 3;
    const int l8 = lane & 7, quad = lane >> 3;
    const int wm = warp & 3, wn = warp >> 2;
    const int row0 = blockIdx.y * 128;
    const int col0 = blockIdx.x * 128;

    const uint32_t aoff = (uint32_t)((((quad & 1) * 8 + l8) * GW + (quad >> 1) * 4) * 4);
    const uint32_t boff = (uint32_t)((((quad >> 1) * 8 + l8) * GW + (quad & 1) * 4) * 4);

    float acc[2][8][4];
    #pragma unroll
    for (int i = 0; i < 2; i++)
        #pragma unroll
        for (int n = 0; n < 8; n++)
            #pragma unroll
            for (int j = 0; j < 4; j++) acc[i][n][j] = 0.0f;

    // prefetch stages 0,1
    #pragma unroll
    for (int s = 0; s < 2; s++) {
        int k0 = s * 64;
        uint32_t sb = smb + (uint32_t)(s * GSTG_WORDS) * 4;
        #pragma unroll
        for (int p = 0; p < 4; p++) {
            int idx = p * 256 + tid, r = idx >> 3, c = idx & 7;
            cp16(sb + (uint32_t)(r * GW + c * 4) * 4, pa.X + (size_t)(row0 + r) * E_ + k0 + c * 8);
        }
        #pragma unroll
        for (int p = 0; p < 4; p++) {
            int idx = p * 256 + tid, r = idx >> 3, c = idx & 7;
            cp16(sb + (uint32_t)(GA_WORDS + r * GW + c * 4) * 4, pa.Wt + (size_t)(col0 + r) * E_ + k0 + c * 8);
        }
        CP_COMMIT();
    }

    int st = 0;  // stage of tile kt
    for (int kt = 0; kt < NKT; kt++) {
        CP_WAIT1();
        __syncthreads();
        if (kt + 2 < NKT) {
            int k0 = (kt + 2) * 64;
            int ns = st + 2; if (ns >= 3) ns -= 3;
            uint32_t sb = smb + (uint32_t)(ns * GSTG_WORDS) * 4;
            #pragma unroll
            for (int p = 0; p < 4; p++) {
                int idx = p * 256 + tid, r = idx >> 3, c = idx & 7;
                cp16(sb + (uint32_t)(r * GW + c * 4) * 4,
                     pa.X + (size_t)(row0 + r) * E_ + k0 + c * 8);
            }
            #pragma unroll
            for (int p = 0; p < 4; p++) {
                int idx = p * 256 + tid, r = idx >> 3, c = idx & 7;
                cp16(sb + (uint32_t)(GA_WORDS + r * GW + c * 4) * 4,
                     pa.Wt + (size_t)(col0 + r) * E_ + k0 + c * 8);
            }
        }
        CP_COMMIT();

        const uint32_t aBuf = smb + (uint32_t)(st * GSTG_WORDS) * 4;
        const uint32_t bBuf = aBuf + GA_WORDS * 4;
        #pragma unroll
        for (int kk = 0; kk < 4; kk++) {
            uint32_t af[2][4];
            LDMX4(af[0][0], af[0][1], af[0][2], af[0][3],
                  aBuf + aoff + (uint32_t)((wm * 32) * GW + kk * 8) * 4);
            LDMX4(af[1][0], af[1][1], af[1][2], af[1][3],
                  aBuf + aoff + (uint32_t)((wm * 32 + 16) * GW + kk * 8) * 4);
            #pragma unroll
            for (int j = 0; j < 4; j++) {
                uint32_t r0, r1, r2, r3;
                LDMX4(r0, r1, r2, r3,
                      bBuf + boff + (uint32_t)((wn * 64 + j * 16) * GW + kk * 8) * 4);
                mma_h(acc[0][2 * j],     af[0], r0, r1);
                mma_h(acc[0][2 * j + 1], af[0], r2, r3);
                mma_h(acc[1][2 * j],     af[1], r0, r1);
                mma_h(acc[1][2 * j + 1], af[1], r2, r3);
            }
        }
        if (++st == 3) st = 0;
    }

    if (!pa.vmode) {
        #pragma unroll
        for (int i = 0; i < 2; i++) {
            int m = row0 + wm * 32 + i * 16;
            int bb = m >> 11, ii = m & 2047;
            #pragma unroll
            for (int n = 0; n < 8; n++) {
                int col = col0 + wn * 64 + n * 8 + 2 * t;
                int h = col >> 6, d = col & 63;
                float2 bi = *reinterpret_cast<const float2*>(pa.bias + col);
                __half* base = pa.out + ((size_t)(bb * H_ + h) * NSEQ) * D_ + d;
                *reinterpret_cast<uint32_t*>(base + (size_t)(ii + g) * D_) =
                    pack_h2(acc[i][n][0] + bi.x, acc[i][n][1] + bi.y);
                *reinterpret_cast<uint32_t*>(base + (size_t)(ii + g + 8) * D_) =
                    pack_h2(acc[i][n][2] + bi.x, acc[i][n][3] + bi.y);
            }
        }
    } else {
        #pragma unroll
        for (int i = 0; i < 2; i++) {
            int m = row0 + wm * 32 + i * 16;
            int bb = m >> 11, ii = m & 2047;
            #pragma unroll
            for (int n = 0; n < 8; n++) {
                int col = col0 + wn * 64 + n * 8 + 2 * t;
                int h = col >> 6, d = col & 63;
                float2 bi = *reinterpret_cast<const float2*>(pa.bias + col);
                __half* base = pa.out + ((size_t)(bb * H_ + h) * D_) * NSEQ;
                base[(size_t)d * NSEQ + ii + g]           = __float2half_rn(acc[i][n][0] + bi.x);
                base[(size_t)(d + 1) * NSEQ + ii + g]     = __float2half_rn(acc[i][n][1] + bi.y);
                base[(size_t)d * NSEQ + ii + g + 8]       = __float2half_rn(acc[i][n][2] + bi.x);
                base[(size_t)(d + 1) * NSEQ + ii + g + 8] = __float2half_rn(acc[i][n][3] + bi.y);
            }
        }
    }
}

__global__ __launch_bounds__(256, 2) void outh_kernel(OArgs2 args)
{
    const OArgs pa = args.p[blockIdx.z];
    extern __shared__ uint32_t smw[];
    const uint32_t smb = smem_u32(smw);

    const int tid  = threadIdx.x;
    const int lane = tid & 31;
    const int warp = tid >> 5;
    const int g = lane >> 2, t = lane & 3;
    const int l8 = lane & 7, quad = lane >> 3;
    const int wm = warp & 3, wn = warp >> 2;
    const int row0 = blockIdx.y * 128;
    const int col0 = blockIdx.x * 128;

    const uint32_t aoff = (uint32_t)((((quad & 1) * 8 + l8) * GW + (quad >> 1) * 4) * 4);
    const uint32_t boff = (uint32_t)((((quad >> 1) * 8 + l8) * GW + (quad & 1) * 4) * 4);

    float acc[2][8][4];
    #pragma unroll
    for (int i = 0; i < 2; i++)
        #pragma unroll
        for (int n = 0; n < 8; n++)
            #pragma unroll
            for (int j = 0; j < 4; j++) acc[i][n][j] = 0.0f;

    #pragma unroll
    for (int s = 0; s < 2; s++) {
        int k0 = s * 64;
        int h = k0 >> 6;
        uint32_t sb = smb + (uint32_t)(s * GSTG_WORDS) * 4;
        #pragma unroll
        for (int p = 0; p < 4; p++) {
            int idx = p * 256 + tid, r = idx >> 3, c = idx & 7;
            int m = row0 + r, bb = m >> 11, ii = m & 2047;
            cp16(sb + (uint32_t)(r * GW + c * 4) * 4,
                 pa.ctx + ((size_t)(bb * H_ + h) * NSEQ + ii) * D_ + c * 8);
        }
        #pragma unroll
        for (int p = 0; p < 4; p++) {
            int idx = p * 256 + tid, r = idx >> 3, c = idx & 7;
            cp16(sb + (uint32_t)(GA_WORDS + r * GW + c * 4) * 4,
                 pa.Wt + (size_t)(col0 + r) * E_ + k0 + c * 8);
        }
        CP_COMMIT();
    }

    int st = 0;
    for (int kt = 0; kt < NKT; kt++) {
        CP_WAIT1();
        __syncthreads();
        if (kt + 2 < NKT) {
            int k0 = (kt + 2) * 64;
            int h = k0 >> 6;
            int ns = st + 2; if (ns >= 3) ns -= 3;
            uint32_t sb = smb + (uint32_t)(ns * GSTG_WORDS) * 4;
            #pragma unroll
            for (int p = 0; p < 4; p++) {
                int idx = p * 256 + tid, r = idx >> 3, c = idx & 7;
                int m = row0 + r, bb = m >> 11, ii = m & 2047;
                cp16(sb + (uint32_t)(r * GW + c * 4) * 4,
                     pa.ctx + ((size_t)(bb * H_ + h) * NSEQ + ii) * D_ + c * 8);
            }
            #pragma unroll
            for (int p = 0; p < 4; p++) {
                int idx = p * 256 + tid, r = idx >> 3, c = idx & 7;
                cp16(sb + (uint32_t)(GA_WORDS + r * GW + c * 4) * 4,
                     pa.Wt + (size_t)(col0 + r) * E_ + k0 + c * 8);
            }
        }
        CP_COMMIT();

        const uint32_t aBuf = smb + (uint32_t)(st * GSTG_WORDS) * 4;
        const uint32_t bBuf = aBuf + GA_WORDS * 4;
        #pragma unroll
        for (int kk = 0; kk < 4; kk++) {
            uint32_t af[2][4];
            LDMX4(af[0][0], af[0][1], af[0][2], af[0][3],
                  aBuf + aoff + (uint32_t)((wm * 32) * GW + kk * 8) * 4);
            LDMX4(af[1][0], af[1][1], af[1][2], af[1][3],
                  aBuf + aoff + (uint32_t)((wm * 32 + 16) * GW + kk * 8) * 4);
            #pragma unroll
            for (int j = 0; j < 4; j++) {
                uint32_t r0, r1, r2, r3;
                LDMX4(r0, r1, r2, r3,
                      bBuf + boff + (uint32_t)((wn * 64 + j * 16) * GW + kk * 8) * 4);
                mma_h(acc[0][2 * j],     af[0], r0, r1);
                mma_h(acc[0][2 * j + 1], af[0], r2, r3);
                mma_h(acc[1][2 * j],     af[1], r0, r1);
                mma_h(acc[1][2 * j + 1], af[1], r2, r3);
            }
        }
        if (++st == 3) st = 0;
    }

    #pragma unroll
    for (int i = 0; i < 2; i++) {
        int m = row0 + wm * 32 + i * 16;
        #pragma unroll
        for (int n = 0; n < 8; n++) {
            int c = col0 + wn * 64 + n * 8 + 2 * t;
            float2 bi = *reinterpret_cast<const float2*>(pa.bias + c);
            float2 lo = { acc[i][n][0] + bi.x, acc[i][n][1] + bi.y };
            float2 hi = { acc[i][n][2] + bi.x, acc[i][n][3] + bi.y };
            *reinterpret_cast<float2*>(pa.out + (size_t)(m + g) * E_ + c) = lo;
            *reinterpret_cast<float2*>(pa.out + (size_t)(m + g + 8) * E_ + c) = hi;
        }
    }
}

// ================= fused flash kernel: register-passed P (round-7 best) ======
#define FQW 36
#define FVW 68
#define FSQ   0
#define FSKa  4608
#define FSVa  13824
#define FLASH_WORDS 22528
#define FLASH_SMEM  (FLASH_WORDS*4)   // 90112 bytes -> 2 CTA/SM

__global__ __launch_bounds__(256, 2) void flashh_kernel(
    const __half* __restrict__ aq, const __half* __restrict__ bq,
    const __half* __restrict__ avt, const __half* __restrict__ bvt,
    __half* __restrict__ actx, __half* __restrict__ bctx)
{
    extern __shared__ uint32_t smw[];
    const uint32_t smb = smem_u32(smw);

    const int tid  = threadIdx.x;
    const int lane = tid & 31;
    const int warp = tid >> 5;
    const int g = lane >> 2, t = lane & 3;
    const int l8 = lane & 7, quad = lane >> 3;
    const int m0 = warp * 16;

    const int side = blockIdx.z;
    const int bh   = blockIdx.y;
    const int row0 = blockIdx.x * 128;

    const __half* Qg  = (side ? bq : aq) + (size_t)bh * NSEQ * D_;
    const __half* Kg  = (side ? aq : bq) + (size_t)bh * NSEQ * D_;
    const __half* Vtg = (side ? avt : bvt) + (size_t)bh * D_ * NSEQ;
    __half* Og = (side ? bctx : actx) + (size_t)bh * NSEQ * D_;

    const uint32_t koff = (uint32_t)((((quad >> 1) * 8 + l8) * FQW + (quad & 1) * 4) * 4);
    const uint32_t voff = (uint32_t)((((quad >> 1) * 8 + l8) * FVW + (quad & 1) * 4) * 4);

    #pragma unroll
    for (int p = 0; p < 4; p++) {
        int idx = p * 256 + tid, r = idx >> 3, c = idx & 7;
        cp16(smb + (uint32_t)(FSQ + r * FQW + c * 4) * 4, Qg + (size_t)(row0 + r) * D_ + c * 8);
    }
    #pragma unroll
    for (int p = 0; p < 4; p++) {
        int idx = p * 256 + tid, r = idx >> 3, c = idx & 7;
        cp16(smb + (uint32_t)(FSKa + r * FQW + c * 4) * 4, Kg + (size_t)r * D_ + c * 8);
    }
    #pragma unroll
    for (int p = 0; p < 4; p++) {
        int idx = p * 256 + tid, r = idx >> 4, c = idx & 15;
        cp16(smb + (uint32_t)(FSVa + r * FVW + c * 4) * 4, Vtg + (size_t)r * NSEQ + c * 8);
    }
    CP_COMMIT();

    uint32_t Qf[4][4];
    float Oacc[8][4];
    #pragma unroll
    for (int n = 0; n < 8; n++)
        #pragma unroll
        for (int j = 0; j < 4; j++) Oacc[n][j] = 0.0f;
    float rsum0 = 0.0f, rsum1 = 0.0f;

    int buf = 0;
    for (int kt = 0; kt < 16; kt++) {
        CP_WAIT0();
        __syncthreads();
        if (kt == 0) {
            #pragma unroll
            for (int kk = 0; kk < 4; kk++) {
                Qf[kk][0] = smw[FSQ + (m0 + g) * FQW + kk * 8 + t];
                Qf[kk][1] = smw[FSQ + (m0 + g + 8) * FQW + kk * 8 + t];
                Qf[kk][2] = smw[FSQ + (m0 + g) * FQW + kk * 8 + t + 4];
                Qf[kk][3] = smw[FSQ + (m0 + g + 8) * FQW + kk * 8 + t + 4];
            }
        }
        if (kt < 15) {
            int key0 = (kt + 1) * 128;
            int nb = buf ^ 1;
            #pragma unroll
            for (int p = 0; p < 4; p++) {
                int idx = p * 256 + tid, r = idx >> 3, c = idx & 7;
                cp16(smb + (uint32_t)(FSKa + nb * 4608 + r * FQW + c * 4) * 4,
                     Kg + (size_t)(key0 + r) * D_ + c * 8);
            }
            #pragma unroll
            for (int p = 0; p < 4; p++) {
                int idx = p * 256 + tid, r = idx >> 4, c = idx & 15;
                cp16(smb + (uint32_t)(FSVa + nb * 4352 + r * FVW + c * 4) * 4,
                     Vtg + (size_t)r * NSEQ + key0 + c * 8);
            }
            CP_COMMIT();
        }

        const uint32_t kbase = smb + (uint32_t)(FSKa + buf * 4608) * 4 + koff;
        const uint32_t vbase = smb + (uint32_t)(FSVa + buf * 4352) * 4 + voff;

        #pragma unroll
        for (int kk = 0; kk < 8; kk++) {
            float slo[4] = {0.f, 0.f, 0.f, 0.f};
            float shi[4] = {0.f, 0.f, 0.f, 0.f};
            #pragma unroll
            for (int c = 0; c < 4; c++) {
                uint32_t r0, r1, r2, r3;
                LDMX4(r0, r1, r2, r3, kbase + (uint32_t)((16 * kk) * FQW + c * 8) * 4);
                mma_h(slo, Qf[c], r0, r1);
                mma_h(shi, Qf[c], r2, r3);
            }
            float e0 = ex2f(slo[0] * CEXP), e1 = ex2f(slo[1] * CEXP);
            float e2 = ex2f(slo[2] * CEXP), e3 = ex2f(slo[3] * CEXP);
            float f0 = ex2f(shi[0] * CEXP), f1 = ex2f(shi[1] * CEXP);
            float f2 = ex2f(shi[2] * CEXP), f3 = ex2f(shi[3] * CEXP);
            rsum0 += (e0 + e1) + (f0 + f1);
            rsum1 += (e2 + e3) + (f2 + f3);
            uint32_t a[4] = { pack_h2(e0, e1), pack_h2(e2, e3),
                              pack_h2(f0, f1), pack_h2(f2, f3) };
            #pragma unroll
            for (int j = 0; j < 4; j++) {
                uint32_t r0, r1, r2, r3;
                LDMX4(r0, r1, r2, r3, vbase + (uint32_t)((16 * j) * FVW + kk * 8) * 4);
                mma_h(Oacc[2 * j],     a, r0, r1);
                mma_h(Oacc[2 * j + 1], a, r2, r3);
            }
        }
        buf ^= 1;
    }

    rsum0 += __shfl_xor_sync(0xffffffffu, rsum0, 1);
    rsum0 += __shfl_xor_sync(0xffffffffu, rsum0, 2);
    rsum1 += __shfl_xor_sync(0xffffffffu, rsum1, 1);
    rsum1 += __shfl_xor_sync(0xffffffffu, rsum1, 2);
    float inv0 = 1.0f / rsum0;
    float inv1 = 1.0f / rsum1;

    __half* r0p = Og + (size_t)(row0 + m0 + g) * D_;
    __half* r1p = Og + (size_t)(row0 + m0 + g + 8) * D_;
    #pragma unroll
    for (int n = 0; n < 8; n++) {
        *reinterpret_cast<uint32_t*>(r0p + n * 8 + 2 * t) =
            pack_h2(Oacc[n][0] * inv0, Oacc[n][1] * inv0);
        *reinterpret_cast<uint32_t*>(r1p + n * 8 + 2 * t) =
            pack_h2(Oacc[n][2] * inv1, Oacc[n][3] * inv1);
    }
}

// ---------------------------------------------------------------------------
extern "C" void kernel_launch(void* const* d_in, const int* in_sizes, int n_in,
                              void* d_out, int out_size)
{
    (void)in_sizes; (void)n_in; (void)out_size;
    const float* a     = (const float*)d_in[0];
    const float* b     = (const float*)d_in[1];
    const float* Wa_qk = (const float*)d_in[2];
    const float* ba_qk = (const float*)d_in[3];
    const float* Wa_v  = (const float*)d_in[4];
    const float* ba_v  = (const float*)d_in[5];
    const float* Wb_qk = (const float*)d_in[6];
    const float* bb_qk = (const float*)d_in[7];
    const float* Wb_v  = (const float*)d_in[8];
    const float* bb_v  = (const float*)d_in[9];
    const float* Wa_o  = (const float*)d_in[10];
    const float* ba_o  = (const float*)d_in[11];
    const float* Wb_o  = (const float*)d_in[12];
    const float* bb_o  = (const float*)d_in[13];
    float* out = (float*)d_out;

    float* scratch = nullptr;
    cudaGetSymbolAddress((void**)&scratch, g_scratch);
    __half* aqh  = (__half*)(scratch + OFF_AQ);
    __half* bqh  = (__half*)(scratch + OFF_BQ);
    __half* avt  = (__half*)(scratch + OFF_AVT);
    __half* bvt  = (__half*)(scratch + OFF_BVT);
    __half* actx = (__half*)(scratch + OFF_ACTX);
    __half* bctx = (__half*)(scratch + OFF_BCTX);
    __half* aTh  = (__half*)(scratch + OFF_ATH);
    __half* bTh  = (__half*)(scratch + OFF_BTH);
    __half* wTh  = (__half*)(scratch + OFF_WT);

    cudaFuncSetAttribute(projh_kernel,  cudaFuncAttributeMaxDynamicSharedMemorySize, GEMM_SMEM);
    cudaFuncSetAttribute(outh_kernel,   cudaFuncAttributeMaxDynamicSharedMemorySize, GEMM_SMEM);
    cudaFuncSetAttribute(flashh_kernel, cudaFuncAttributeMaxDynamicSharedMemorySize, FLASH_SMEM);

    PrepArgs prep = { a, b, Wa_qk, Wa_v, Wb_qk, Wb_v, Wa_o, Wb_o, aTh, bTh, wTh };
    prep_kernel<<<dim3(32, 32, 8), 256>>>(prep);

    PArgs4 pargs;
    pargs.p[0] = { aTh, wTh + 0 * 1048576, ba_qk, aqh, 0 };
    pargs.p[1] = { aTh, wTh + 1 * 1048576, ba_v,  avt, 1 };
    pargs.p[2] = { bTh, wTh + 2 * 1048576, bb_qk, bqh, 0 };
    pargs.p[3] = { bTh, wTh + 3 * 1048576, bb_v,  bvt, 1 };
    projh_kernel<<<dim3(E_ / 128, (B_ * NSEQ) / 128, 4), 256, GEMM_SMEM>>>(pargs);

    flashh_kernel<<<dim3(16, BH_, 2), 256, FLASH_SMEM>>>(aqh, bqh, avt, bvt, actx, bctx);

    OArgs2 oargs;
    oargs.p[0] = { actx, wTh + 4 * 1048576, ba_o, out };
    oargs.p[1] = { bctx, wTh + 5 * 1048576, bb_o, out + (size_t)B_ * NSEQ * E_ };
    outh_kernel<<<dim3(E_ / 128, (B_ * NSEQ) / 128, 2), 256, GEMM_SMEM>>>(oargs);
}